// round 2
// baseline (speedup 1.0000x reference)
#include <cuda_runtime.h>
#include <math.h>

#define TT 215
#define BB 256
#define NTOK (TT*BB)      // 55040
#define DT 72

// ---------------- scratch (device globals, alloc-free) ----------------
__device__ float g_h[NTOK*DT];        // running hidden state [T,B,72]
__device__ float g_tmp[NTOK*216];     // qkv (216) / ff1 (128) scratch
__device__ float g_ctx[NTOK*DT];      // attention context
__device__ float g_qkvg[3*36*BB*36];  // graph q,k,v  [m][node][b][e]
__device__ float g_AT[1296*BB];       // graph attention flattened, [e][b]
__device__ float g_sq[BB];
__device__ float g_part[BB];
__device__ float g_Wc[4*36*36];       // combined q/k/v/skip weights
__device__ float g_bc[4*36];

__device__ __forceinline__ float warp_sum(float v){
  #pragma unroll
  for (int o=16;o;o>>=1) v += __shfl_xor_sync(0xffffffffu,v,o);
  return v;
}
__device__ __forceinline__ float warp_max(float v){
  #pragma unroll
  for (int o=16;o;o>>=1) v = fmaxf(v,__shfl_xor_sync(0xffffffffu,v,o));
  return v;
}

// ---------------- 0: fold x-projection (src@Wenc.T+benc)*6 into q/k/v/skip ----------------
__global__ void k_combine(const float* __restrict__ Wq, const float* __restrict__ bq,
                          const float* __restrict__ Wk, const float* __restrict__ bk,
                          const float* __restrict__ Wv, const float* __restrict__ bv,
                          const float* __restrict__ Ws, const float* __restrict__ bs,
                          const float* __restrict__ Wenc, const float* __restrict__ benc){
  const float* Wm[4] = {Wq,Wk,Wv,Ws};
  const float* bm[4] = {bq,bk,bv,bs};
  for (int idx = threadIdx.x; idx < 4*36*36; idx += blockDim.x){
    int m = idx/1296, r = idx%1296, e = r/36, i = r%36;
    float acc = 0.f;
    for (int kk=0; kk<36; kk++) acc += Wm[m][e*36+kk]*Wenc[kk*36+i];
    g_Wc[idx] = 6.0f*acc;
  }
  for (int idx = threadIdx.x; idx < 4*36; idx += blockDim.x){
    int m = idx/36, e = idx%36;
    float acc = 0.f;
    for (int kk=0; kk<36; kk++) acc += Wm[m][e*36+kk]*benc[kk];
    g_bc[idx] = 6.0f*acc + bm[m][e];
  }
}

// ---------------- 1: skip -> h[:, :36], pe -> h[:, 36:], graph qkv for t<36 ----------------
__global__ void k_embed(const float* __restrict__ src, const float* __restrict__ times){
  int t = blockIdx.x;
  int b0 = blockIdx.y * 128;
  __shared__ float Wcs[4*36*37];
  __shared__ float bcs[4*36];
  __shared__ float srcs[128*36];
  __shared__ float ts_s[18];
  int tid = threadIdx.x;
  for (int idx=tid; idx<4*36*36; idx+=256){
    int me = idx/36, i = idx%36;
    Wcs[me*37+i] = g_Wc[idx];
  }
  for (int idx=tid; idx<4*36; idx+=256) bcs[idx] = g_bc[idx];
  if (tid < 18) ts_s[tid] = (float)pow(215.0, (double)tid/17.0);
  for (int idx=tid; idx<128*36; idx+=256){
    int bl = idx/36, i = idx%36;
    srcs[bl*36+i] = src[((long)(t*BB + b0 + bl))*72 + i];
  }
  __syncthreads();
  for (int idx=tid; idx<128*36; idx+=256){
    int bl = idx/36, e = idx%36;
    int b = b0 + bl;
    const float* sr = &srcs[bl*36];
    // skip (m=3)
    {
      float acc = bcs[3*36+e];
      const float* wr = &Wcs[(3*36+e)*37];
      #pragma unroll
      for (int i=0;i<36;i++) acc = fmaf(sr[i], wr[i], acc);
      g_h[((long)(t*BB+b))*DT + e] = acc;
    }
    // positional encoding
    {
      float tv = times[t*BB+b];
      float pe = (e<18) ? sinf(tv/ts_s[e]) : cosf(tv/ts_s[e-18]);
      g_h[((long)(t*BB+b))*DT + 36 + e] = pe;
    }
    if (t < 36){
      #pragma unroll
      for (int m=0;m<3;m++){
        float acc = bcs[m*36+e];
        const float* wr = &Wcs[(m*36+e)*37];
        #pragma unroll
        for (int i=0;i<36;i++) acc = fmaf(sr[i], wr[i], acc);
        g_qkvg[(((long)m*36+t)*BB + b)*36 + e] = acc;
      }
    }
  }
}

// ---------------- 2: graph attention per batch (36x36) ----------------
__global__ void k_graph(){
  __shared__ float qs[36*37], ks[36*37], vs[36*37], As[36*37];
  __shared__ float red[256];
  int b = blockIdx.x, tid = threadIdx.x;
  for (int idx=tid; idx<1296; idx+=256){
    int n = idx/36, e = idx%36;
    qs[n*37+e] = g_qkvg[((0L*36+n)*BB + b)*36 + e];
    ks[n*37+e] = g_qkvg[((1L*36+n)*BB + b)*36 + e];
    vs[n*37+e] = g_qkvg[((2L*36+n)*BB + b)*36 + e];
  }
  __syncthreads();
  for (int idx=tid; idx<1296; idx+=256){
    int i = idx/36, j = idx%36;
    float acc = 0.f;
    #pragma unroll
    for (int e=0;e<36;e++) acc = fmaf(qs[i*37+e], ks[j*37+e], acc);
    As[i*37+j] = acc*(1.0f/6.0f);
  }
  __syncthreads();
  int warp = tid/32, lane = tid%32;
  for (int i=warp; i<36; i+=8){
    float v1 = As[i*37+lane];
    float v2 = (lane<4) ? As[i*37+32+lane] : -3e38f;
    float mx = warp_max(fmaxf(v1,v2));
    float p1 = __expf(v1-mx);
    float p2 = (lane<4) ? __expf(v2-mx) : 0.f;
    float s = warp_sum(p1+p2);
    float inv = 1.f/s;
    As[i*37+lane] = p1*inv;
    if (lane<4) As[i*37+32+lane] = p2*inv;
  }
  __syncthreads();
  float sqacc = 0.f;
  for (int idx=tid; idx<1296; idx+=256){
    int i = idx/36, j = idx%36;
    float a = As[i*37+j];
    g_AT[(long)idx*BB + b] = a;
    sqacc += a*a;
  }
  red[tid] = sqacc; __syncthreads();
  for (int s2=128; s2>0; s2>>=1){
    if (tid<s2) red[tid]+=red[tid+s2];
    __syncthreads();
  }
  if (tid==0) g_sq[b] = red[0];
  for (int idx=tid; idx<1296; idx+=256){
    int i = idx/36, e = idx%36;
    float acc = 0.f;
    #pragma unroll
    for (int j=0;j<36;j++) acc = fmaf(As[i*37+j], vs[j*37+e], acc);
    g_h[((long)(i*BB+b))*DT + e] += acc;
  }
}

// ---------------- 3: gram / pairwise distance partials ----------------
__global__ void k_gram(){
  __shared__ float ar[1296];
  __shared__ float red[256];
  int b1 = blockIdx.x, tid = threadIdx.x;
  for (int e=tid; e<1296; e+=256) ar[e] = g_AT[(long)e*BB + b1];
  __syncthreads();
  int b2 = tid;
  float dot = 0.f;
  for (int e=0;e<1296;e++) dot = fmaf(ar[e], g_AT[(long)e*BB + b2], dot);
  float d2 = g_sq[b1] + g_sq[b2] - 2.0f*dot;
  d2 = fmaxf(d2, 0.f);
  float c = (d2 > 0.f) ? sqrtf(d2) : 0.f;
  red[tid] = c; __syncthreads();
  for (int s2=128; s2>0; s2>>=1){
    if (tid<s2) red[tid]+=red[tid+s2];
    __syncthreads();
  }
  if (tid==0) g_part[b1] = red[0];
}

__global__ void k_distfin(float* __restrict__ out, int out_size){
  __shared__ float red[256];
  int tid = threadIdx.x;
  red[tid] = g_part[tid]; __syncthreads();
  for (int s2=128; s2>0; s2>>=1){
    if (tid<s2) red[tid]+=red[tid+s2];
    __syncthreads();
  }
  if (tid==0) out[out_size-1] = red[0] * (1.0f/65536.0f);
}

// ---------------- generic smem GEMM: C[tok, yBase+o] = A[tok]@W.T + b ----------------
template<int K, int OC, int NT, bool RELU>
__global__ void k_gemm(const float* __restrict__ A, const float* __restrict__ W,
                       const float* __restrict__ bias, float* __restrict__ C, int ldc){
  constexpr int KP = K+1;
  constexpr int TPT = 256/NT;
  constexpr int R = (OC + TPT - 1)/TPT;
  __shared__ float Ws[OC*KP];
  __shared__ float As[NT*KP];
  int tid = threadIdx.x;
  long tokBase = (long)blockIdx.x*NT;
  const float* Wp = W + (long)blockIdx.y*OC*K;
  for (int idx=tid; idx<OC*K; idx+=256){ int o=idx/K, kk=idx%K; Ws[o*KP+kk]=Wp[idx]; }
  for (int idx=tid; idx<NT*K; idx+=256){ int tk=idx/K, kk=idx%K; As[tk*KP+kk]=A[(tokBase+tk)*K+kk]; }
  __syncthreads();
  int tok = tid / TPT, ol = tid % TPT;
  float acc[R];
  #pragma unroll
  for (int r=0;r<R;r++){ int o=ol+r*TPT; acc[r] = (o<OC) ? bias[blockIdx.y*OC+o] : 0.f; }
  #pragma unroll 4
  for (int kk=0;kk<K;kk++){
    float a = As[tok*KP+kk];
    #pragma unroll
    for (int r=0;r<R;r++){ int o=ol+r*TPT; if (o<OC) acc[r] = fmaf(a, Ws[o*KP+kk], acc[r]); }
  }
  float* Crow = C + (tokBase+tok)*ldc + blockIdx.y*OC;
  #pragma unroll
  for (int r=0;r<R;r++){
    int o=ol+r*TPT;
    if (o<OC) Crow[o] = RELU ? fmaxf(acc[r],0.f) : acc[r];
  }
}

// ---------------- GEMM + residual(g_h) + LayerNorm fused, writes g_h ----------------
template<int K, int NT>
__global__ void k_gemm_ln(const float* __restrict__ A, const float* __restrict__ W,
                          const float* __restrict__ bias, const float* __restrict__ gam,
                          const float* __restrict__ bet){
  constexpr int KP = K+1;
  constexpr int TPT = 256/NT;
  constexpr int R = (72 + TPT - 1)/TPT;
  __shared__ float Ws[72*KP];
  __shared__ float As[NT*KP];
  __shared__ float Ys[NT*73];
  int tid = threadIdx.x;
  long tokBase = (long)blockIdx.x*NT;
  for (int idx=tid; idx<72*K; idx+=256){ int o=idx/K, kk=idx%K; Ws[o*KP+kk]=W[idx]; }
  for (int idx=tid; idx<NT*K; idx+=256){ int tk=idx/K, kk=idx%K; As[tk*KP+kk]=A[(tokBase+tk)*K+kk]; }
  __syncthreads();
  int tok = tid / TPT, ol = tid % TPT;
  float acc[R];
  #pragma unroll
  for (int r=0;r<R;r++){ int o=ol+r*TPT; acc[r] = (o<72) ? bias[o] : 0.f; }
  #pragma unroll 4
  for (int kk=0;kk<K;kk++){
    float a = As[tok*KP+kk];
    #pragma unroll
    for (int r=0;r<R;r++){ int o=ol+r*TPT; if (o<72) acc[r] = fmaf(a, Ws[o*KP+kk], acc[r]); }
  }
  const float* hres = g_h + (tokBase+tok)*72;
  #pragma unroll
  for (int r=0;r<R;r++){ int o=ol+r*TPT; if (o<72) Ys[tok*73+o] = hres[o] + acc[r]; }
  __syncthreads();
  int warp = tid/32, lane = tid%32;
  for (int tk=warp; tk<NT; tk+=8){
    float* y = &Ys[tk*73];
    float x0=y[lane], x1=y[lane+32], x2=(lane<8)?y[lane+64]:0.f;
    float mu = warp_sum(x0+x1+x2)*(1.0f/72.0f);
    float d0=x0-mu, d1=x1-mu, d2=(lane<8)?(x2-mu):0.f;
    float var = warp_sum(d0*d0+d1*d1+d2*d2)*(1.0f/72.0f);
    float rstd = rsqrtf(var+1e-5f);
    float* hout = g_h + (tokBase+tk)*72;
    hout[lane]    = d0*rstd*gam[lane]   + bet[lane];
    hout[lane+32] = d1*rstd*gam[lane+32]+ bet[lane+32];
    if (lane<8) hout[lane+64] = d2*rstd*gam[lane+64]+bet[lane+64];
  }
}

// ---------------- encoder attention: one block per (b, head) ----------------
__global__ void k_attn(const float* __restrict__ qkv, const int* __restrict__ lengths){
  __shared__ float Ks[TT*19];
  __shared__ float Vs[TT*19];
  int b = blockIdx.x, h = blockIdx.y;
  int len = lengths[b];
  int tid = threadIdx.x;
  for (int idx=tid; idx<TT*18; idx+=256){
    int t = idx/18, d = idx%18;
    const float* row = qkv + ((long)(t*BB+b))*216 + h*18;
    Ks[t*19+d] = row[72+d];
    Vs[t*19+d] = row[144+d];
  }
  __syncthreads();
  int warp = tid/32, lane = tid%32;
  const float scale = 0.23570226039551584f; // 1/sqrt(18)
  for (int t=warp; t<TT; t+=8){
    const float* qrow = qkv + ((long)(t*BB+b))*216 + h*18;
    float q[18];
    #pragma unroll
    for (int d=0;d<18;d++) q[d] = qrow[d];
    float sc[7];
    float mx = -3.0e38f;
    #pragma unroll
    for (int k2=0;k2<7;k2++){
      int s = lane + 32*k2;
      float val = -3.0e38f;
      if (s < TT){
        float a = 0.f;
        #pragma unroll
        for (int d=0;d<18;d++) a = fmaf(q[d], Ks[s*19+d], a);
        val = a*scale + ((s>=len) ? -1e9f : 0.f);
      }
      sc[k2] = val;
      mx = fmaxf(mx, val);
    }
    mx = warp_max(mx);
    float l = 0.f;
    float ctx[18];
    #pragma unroll
    for (int d=0;d<18;d++) ctx[d]=0.f;
    #pragma unroll
    for (int k2=0;k2<7;k2++){
      int s = lane + 32*k2;
      if (s < TT){
        float p = __expf(sc[k2]-mx);
        l += p;
        #pragma unroll
        for (int d=0;d<18;d++) ctx[d] = fmaf(p, Vs[s*19+d], ctx[d]);
      }
    }
    l = warp_sum(l);
    #pragma unroll
    for (int d=0;d<18;d++) ctx[d] = warp_sum(ctx[d]);
    if (lane==0){
      float inv = 1.f/l;
      float* o = g_ctx + ((long)(t*BB+b))*72 + h*18;
      #pragma unroll
      for (int d=0;d<18;d++) o[d] = ctx[d]*inv;
    }
  }
}

// ---------------- pooling + static emb + MLP head ----------------
__global__ void k_head(const float* __restrict__ statp, const int* __restrict__ lengths,
                       const float* __restrict__ W_emb, const float* __restrict__ b_emb,
                       const float* __restrict__ w1, const float* __restrict__ b1,
                       const float* __restrict__ w2, const float* __restrict__ b2,
                       float* __restrict__ out){
  __shared__ float feat[108];
  __shared__ float hid[108];
  __shared__ float st[9];
  int b = blockIdx.x, tid = threadIdx.x;
  int len = lengths[b];
  if (tid < 9) st[tid] = statp[b*9+tid];
  __syncthreads();
  if (tid < 36){
    float acc = b_emb[tid];
    #pragma unroll
    for (int i=0;i<9;i++) acc = fmaf(st[i], W_emb[tid*9+i], acc);
    feat[72+tid] = acc;
  }
  if (tid < 72){
    float acc = 0.f;
    for (int t=0;t<len;t++) acc += g_h[((long)(t*BB+b))*72 + tid];
    feat[tid] = acc / ((float)len + 1.0f);
  }
  __syncthreads();
  for (int o=tid; o<108; o+=blockDim.x){
    float acc = b1[o];
    #pragma unroll 4
    for (int i=0;i<108;i++) acc = fmaf(feat[i], w1[o*108+i], acc);
    hid[o] = fmaxf(acc, 0.f);
  }
  __syncthreads();
  if (tid < 2){
    float acc = b2[tid];
    for (int i=0;i<108;i++) acc = fmaf(hid[i], w2[tid*108+i], acc);
    out[b*2+tid] = acc;
  }
}

// ---------------- host ----------------
extern "C" void kernel_launch(void* const* d_in, const int* in_sizes, int n_in,
                              void* d_out, int out_size){
  const float* src     = (const float*)d_in[0];
  const float* statp   = (const float*)d_in[1];
  const float* times   = (const float*)d_in[2];
  const int*   lengths = (const int*)  d_in[3];
  const float* W_enc   = (const float*)d_in[4];
  const float* b_enc   = (const float*)d_in[5];
  const float* W_emb   = (const float*)d_in[6];
  const float* b_emb   = (const float*)d_in[7];
  const float* Wq      = (const float*)d_in[8];
  const float* bq      = (const float*)d_in[9];
  const float* Wk      = (const float*)d_in[10];
  const float* bk      = (const float*)d_in[11];
  const float* Wv      = (const float*)d_in[12];
  const float* bv      = (const float*)d_in[13];
  const float* Wskip   = (const float*)d_in[14];
  const float* bskip   = (const float*)d_in[15];
  const float* enc_in_w  = (const float*)d_in[16];
  const float* enc_in_b  = (const float*)d_in[17];
  const float* enc_out_w = (const float*)d_in[18];
  const float* enc_out_b = (const float*)d_in[19];
  const float* ff1w    = (const float*)d_in[20];
  const float* ff1b    = (const float*)d_in[21];
  const float* ff2w    = (const float*)d_in[22];
  const float* ff2b    = (const float*)d_in[23];
  const float* ln1g    = (const float*)d_in[24];
  const float* ln1b    = (const float*)d_in[25];
  const float* ln2g    = (const float*)d_in[26];
  const float* ln2b    = (const float*)d_in[27];
  const float* mlp_w1  = (const float*)d_in[28];
  const float* mlp_b1  = (const float*)d_in[29];
  const float* mlp_w2  = (const float*)d_in[30];
  const float* mlp_b2  = (const float*)d_in[31];
  float* out = (float*)d_out;

  float *hB, *tmpB, *ctxB;
  cudaGetSymbolAddress((void**)&hB,   g_h);
  cudaGetSymbolAddress((void**)&tmpB, g_tmp);
  cudaGetSymbolAddress((void**)&ctxB, g_ctx);

  k_combine<<<1,256>>>(Wq,bq,Wk,bk,Wv,bv,Wskip,bskip,W_enc,b_enc);
  k_embed<<<dim3(TT,2),256>>>(src, times);
  k_graph<<<BB,256>>>();
  k_gram<<<BB,256>>>();

  for (int l=0; l<2; l++){
    // qkv: [55040,72] @ [216,72]^T -> [55040,216]
    k_gemm<72,72,32,false><<<dim3(NTOK/32,3),256>>>(hB, enc_in_w + (long)l*216*72,
                                                    enc_in_b + l*216, tmpB, 216);
    k_attn<<<dim3(BB,4),256>>>(tmpB, lengths);
    // out-proj + residual + LN1
    k_gemm_ln<72,32><<<NTOK/32,256>>>(ctxB, enc_out_w + (long)l*72*72,
                                      enc_out_b + l*72, ln1g + l*72, ln1b + l*72);
    // ff1 (relu): [55040,72] @ [128,72]^T -> [55040,128]
    k_gemm<72,128,32,true><<<dim3(NTOK/32,1),256>>>(hB, ff1w + (long)l*128*72,
                                                    ff1b + l*128, tmpB, 128);
    // ff2 + residual + LN2
    k_gemm_ln<128,8><<<NTOK/8,256>>>(tmpB, ff2w + (long)l*72*128,
                                     ff2b + l*72, ln2g + l*72, ln2b + l*72);
  }

  k_head<<<BB,128>>>(statp, lengths, W_emb, b_emb, mlp_w1, mlp_b1, mlp_w2, mlp_b2, out);
  k_distfin<<<1,256>>>(out, out_size);
}

// round 3
// speedup vs baseline: 2.1737x; 2.1737x over previous
#include <cuda_runtime.h>
#include <math.h>

#define TT 215
#define BB 256
#define NTOK (TT*BB)      // 55040
#define DT 72

// ---------------- scratch (device globals, alloc-free) ----------------
__device__ float g_h[NTOK*DT];        // hidden state [b][t][72]
__device__ float g_tmp[NTOK*216];     // qkv (216) / ff1 (128) scratch [b][t][*]
__device__ float g_ctx[NTOK*DT];      // attention context [b][t][72]
__device__ float g_qkvg[3*36*BB*36];  // graph q,k,v  [m][node][b][e]
__device__ float g_AT[1296*BB];       // graph attention flattened, [e][b]
__device__ float g_sq[BB];
__device__ float g_part[BB];
__device__ float g_Wc[4*36*36];       // combined q/k/v/skip weights
__device__ float g_bc[4*36];

__device__ __forceinline__ float warp_sum(float v){
  #pragma unroll
  for (int o=16;o;o>>=1) v += __shfl_xor_sync(0xffffffffu,v,o);
  return v;
}
__device__ __forceinline__ float warp_max(float v){
  #pragma unroll
  for (int o=16;o;o>>=1) v = fmaxf(v,__shfl_xor_sync(0xffffffffu,v,o));
  return v;
}

// ---------------- 0: fold x-projection (src@Wenc.T+benc)*6 into q/k/v/skip ----------------
__global__ void k_combine(const float* __restrict__ Wq, const float* __restrict__ bq,
                          const float* __restrict__ Wk, const float* __restrict__ bk,
                          const float* __restrict__ Wv, const float* __restrict__ bv,
                          const float* __restrict__ Ws, const float* __restrict__ bs,
                          const float* __restrict__ Wenc, const float* __restrict__ benc){
  const float* Wm[4] = {Wq,Wk,Wv,Ws};
  const float* bm[4] = {bq,bk,bv,bs};
  for (int idx = threadIdx.x; idx < 4*36*36; idx += blockDim.x){
    int m = idx/1296, r = idx%1296, e = r/36, i = r%36;
    float acc = 0.f;
    for (int kk=0; kk<36; kk++) acc += Wm[m][e*36+kk]*Wenc[kk*36+i];
    g_Wc[idx] = 6.0f*acc;
  }
  for (int idx = threadIdx.x; idx < 4*36; idx += blockDim.x){
    int m = idx/36, e = idx%36;
    float acc = 0.f;
    for (int kk=0; kk<36; kk++) acc += Wm[m][e*36+kk]*benc[kk];
    g_bc[idx] = 6.0f*acc + bm[m][e];
  }
}

// ---------------- 1: skip -> h[:,:36], pe -> h[:,36:], graph qkv for t<36 ----------------
// grid (215, 2), block 128: thread = one batch element
__global__ __launch_bounds__(128) void k_embed(const float* __restrict__ src,
                                               const float* __restrict__ times){
  __shared__ float Wt[4*36*36];   // [m][i][e] transposed
  __shared__ float bcs[4*36];
  __shared__ float srcs[128*37];
  __shared__ float ts_s[18];
  int t = blockIdx.x; int b0 = blockIdx.y*128; int tid = threadIdx.x;
  for (int idx=tid; idx<4*1296; idx+=128){
    int m = idx/1296, r = idx%1296, e = r/36, i2 = r%36;
    Wt[m*1296 + i2*36 + e] = g_Wc[m*1296 + e*36 + i2];
  }
  for (int idx=tid; idx<144; idx+=128) bcs[idx]=g_bc[idx];
  if (tid<18) ts_s[tid] = (float)pow(215.0,(double)tid/17.0);
  for (int idx=tid; idx<128*36; idx+=128){
    int bl = idx/36, i2 = idx%36;
    srcs[bl*37+i2] = src[((long)t*BB + b0+bl)*72 + i2];
  }
  __syncthreads();
  int b = b0 + tid;
  float sr[36];
  #pragma unroll
  for (int i2=0;i2<36;i2++) sr[i2] = srcs[tid*37+i2];
  float tv = times[(long)t*BB + b];
  float* hrow = &g_h[((long)b*TT + t)*DT];
  #pragma unroll
  for (int d=0; d<18; d++){
    float s, c; sincosf(tv/ts_s[d], &s, &c);
    hrow[36+d] = s; hrow[54+d] = c;
  }
  int mmax = (t<36) ? 4 : 1;
  for (int mm=0; mm<mmax; mm++){
    int m = (mm==0)?3:(mm-1);
    float acc[36];
    #pragma unroll
    for (int e=0;e<36;e++) acc[e] = bcs[m*36+e];
    #pragma unroll
    for (int kk=0;kk<36;kk++){
      float a = sr[kk];
      const float4* wr = (const float4*)&Wt[m*1296 + kk*36];
      #pragma unroll
      for (int j=0;j<9;j++){
        float4 w4 = wr[j];
        acc[4*j+0] = fmaf(a, w4.x, acc[4*j+0]);
        acc[4*j+1] = fmaf(a, w4.y, acc[4*j+1]);
        acc[4*j+2] = fmaf(a, w4.z, acc[4*j+2]);
        acc[4*j+3] = fmaf(a, w4.w, acc[4*j+3]);
      }
    }
    if (m == 3){
      float4* o = (float4*)hrow;
      #pragma unroll
      for (int j=0;j<9;j++){ float4 v; v.x=acc[4*j]; v.y=acc[4*j+1]; v.z=acc[4*j+2]; v.w=acc[4*j+3]; o[j]=v; }
    } else {
      float4* o = (float4*)&g_qkvg[(((long)m*36+t)*BB + b)*36];
      #pragma unroll
      for (int j=0;j<9;j++){ float4 v; v.x=acc[4*j]; v.y=acc[4*j+1]; v.z=acc[4*j+2]; v.w=acc[4*j+3]; o[j]=v; }
    }
  }
}

// ---------------- 2: graph attention per batch (36x36) ----------------
__global__ void k_graph(){
  __shared__ float qs[36*37], ks[36*37], vs[36*37], As[36*37];
  __shared__ float red[256];
  int b = blockIdx.x, tid = threadIdx.x;
  for (int idx=tid; idx<1296; idx+=256){
    int n = idx/36, e = idx%36;
    qs[n*37+e] = g_qkvg[((0L*36+n)*BB + b)*36 + e];
    ks[n*37+e] = g_qkvg[((1L*36+n)*BB + b)*36 + e];
    vs[n*37+e] = g_qkvg[((2L*36+n)*BB + b)*36 + e];
  }
  __syncthreads();
  for (int idx=tid; idx<1296; idx+=256){
    int i = idx/36, j = idx%36;
    float acc = 0.f;
    #pragma unroll
    for (int e=0;e<36;e++) acc = fmaf(qs[i*37+e], ks[j*37+e], acc);
    As[i*37+j] = acc*(1.0f/6.0f);
  }
  __syncthreads();
  int warp = tid/32, lane = tid%32;
  for (int i=warp; i<36; i+=8){
    float v1 = As[i*37+lane];
    float v2 = (lane<4) ? As[i*37+32+lane] : -3e38f;
    float mx = warp_max(fmaxf(v1,v2));
    float p1 = __expf(v1-mx);
    float p2 = (lane<4) ? __expf(v2-mx) : 0.f;
    float s = warp_sum(p1+p2);
    float inv = 1.f/s;
    As[i*37+lane] = p1*inv;
    if (lane<4) As[i*37+32+lane] = p2*inv;
  }
  __syncthreads();
  float sqacc = 0.f;
  for (int idx=tid; idx<1296; idx+=256){
    int i = idx/36, j = idx%36;
    float a = As[i*37+j];
    g_AT[(long)idx*BB + b] = a;
    sqacc += a*a;
  }
  red[tid] = sqacc; __syncthreads();
  for (int s2=128; s2>0; s2>>=1){
    if (tid<s2) red[tid]+=red[tid+s2];
    __syncthreads();
  }
  if (tid==0) g_sq[b] = red[0];
  for (int idx=tid; idx<1296; idx+=256){
    int i = idx/36, e = idx%36;
    float acc = 0.f;
    #pragma unroll
    for (int j=0;j<36;j++) acc = fmaf(As[i*37+j], vs[j*37+e], acc);
    g_h[((long)(b*TT + i))*DT + e] += acc;
  }
}

// ---------------- 3: gram / pairwise distance partials ----------------
__global__ void k_gram(){
  __shared__ float ar[1296];
  __shared__ float red[256];
  int b1 = blockIdx.x, tid = threadIdx.x;
  for (int e=tid; e<1296; e+=256) ar[e] = g_AT[(long)e*BB + b1];
  __syncthreads();
  int b2 = tid;
  float d0=0.f,d1=0.f,d2a=0.f,d3=0.f;
  for (int e=0;e<1296;e+=4){
    d0 = fmaf(ar[e+0], g_AT[(long)(e+0)*BB + b2], d0);
    d1 = fmaf(ar[e+1], g_AT[(long)(e+1)*BB + b2], d1);
    d2a= fmaf(ar[e+2], g_AT[(long)(e+2)*BB + b2], d2a);
    d3 = fmaf(ar[e+3], g_AT[(long)(e+3)*BB + b2], d3);
  }
  float dot = (d0+d1)+(d2a+d3);
  float d2 = g_sq[b1] + g_sq[b2] - 2.0f*dot;
  d2 = fmaxf(d2, 0.f);
  float c = (d2 > 0.f) ? sqrtf(d2) : 0.f;
  red[tid] = c; __syncthreads();
  for (int s2=128; s2>0; s2>>=1){
    if (tid<s2) red[tid]+=red[tid+s2];
    __syncthreads();
  }
  if (tid==0) g_part[b1] = red[0];
}

__global__ void k_distfin(float* __restrict__ out, int out_size){
  __shared__ float red[256];
  int tid = threadIdx.x;
  red[tid] = g_part[tid]; __syncthreads();
  for (int s2=128; s2>0; s2>>=1){
    if (tid<s2) red[tid]+=red[tid+s2];
    __syncthreads();
  }
  if (tid==0) out[out_size-1] = red[0] * (1.0f/65536.0f);
}

// ---------------- register-tiled GEMM: C = A@W.T + b, [b][t] layout, pad-skipping ----
// BM=128 tokens, TM=8 (strided by 16), TN=4; blockDim = 16*NOG.
template<int K, int OC, int NOG, bool RELU>
__global__ __launch_bounds__(512) void k_gemm_rt(
    const float* __restrict__ A, const float* __restrict__ W,
    const float* __restrict__ bias, float* __restrict__ C,
    int ldc, const int* __restrict__ lengths){
  extern __shared__ float sm[];
  float* Ws = sm;                 // [K][OC] transposed
  float* As = sm + K*OC;          // [128][K]
  const int b = blockIdx.y;
  const int len = lengths[b];
  const int t0 = blockIdx.x*128;
  if (t0 >= len) return;
  int navail = TT - t0; if (navail > 128) navail = 128;
  int nact = len - t0; if (nact > navail) nact = navail;
  const int tid = threadIdx.x;
  const int z = blockIdx.z;
  const float* Wp = W + (long)z*OC*K;
  for (int idx = tid; idx < OC*K; idx += blockDim.x){
    int o = idx / K, kk = idx % K;
    Ws[kk*OC + o] = Wp[idx];
  }
  const float* Ab = A + ((long)(b*TT + t0))*K;
  for (int idx = tid; idx < 128*K; idx += blockDim.x){
    int r = idx / K;
    As[idx] = (r < nact) ? Ab[idx] : 0.f;
  }
  __syncthreads();
  const int og = tid % NOG, tg = tid / NOG;
  float acc[8][4];
  #pragma unroll
  for (int m=0;m<8;m++){ acc[m][0]=0.f;acc[m][1]=0.f;acc[m][2]=0.f;acc[m][3]=0.f; }
  #pragma unroll 4
  for (int kk=0; kk<K; kk++){
    float4 w4 = *(const float4*)&Ws[kk*OC + og*4];
    #pragma unroll
    for (int m=0;m<8;m++){
      float a = As[(tg + 16*m)*K + kk];
      acc[m][0] = fmaf(a, w4.x, acc[m][0]);
      acc[m][1] = fmaf(a, w4.y, acc[m][1]);
      acc[m][2] = fmaf(a, w4.z, acc[m][2]);
      acc[m][3] = fmaf(a, w4.w, acc[m][3]);
    }
  }
  float4 bv = *(const float4*)&bias[(long)z*OC + og*4];
  #pragma unroll
  for (int m=0;m<8;m++){
    int r = tg + 16*m;
    if (r < nact){
      float4 o4;
      o4.x = acc[m][0]+bv.x; o4.y = acc[m][1]+bv.y;
      o4.z = acc[m][2]+bv.z; o4.w = acc[m][3]+bv.w;
      if (RELU){ o4.x=fmaxf(o4.x,0.f); o4.y=fmaxf(o4.y,0.f); o4.z=fmaxf(o4.z,0.f); o4.w=fmaxf(o4.w,0.f); }
      *(float4*)&C[((long)(b*TT + t0 + r))*ldc + z*OC + og*4] = o4;
    }
  }
}

// ---------------- GEMM + residual(g_h) + LayerNorm fused -> g_h ----------------
// OC=72, NOG=18, blockDim 288. As has pad stride KP=K+1; Ys aliases As (stride 73).
template<int K>
__global__ __launch_bounds__(288) void k_gemmln_rt(
    const float* __restrict__ A, const float* __restrict__ W,
    const float* __restrict__ bias, const float* __restrict__ gam,
    const float* __restrict__ bet, const int* __restrict__ lengths){
  constexpr int KP = K+1;
  extern __shared__ float sm[];
  float* Ws = sm;                 // [K][72]
  float* As = sm + K*72;          // [128][KP]
  const int b = blockIdx.y;
  const int len = lengths[b];
  const int t0 = blockIdx.x*128;
  if (t0 >= len) return;
  int navail = TT - t0; if (navail > 128) navail = 128;
  int nact = len - t0; if (nact > navail) nact = navail;
  const int tid = threadIdx.x;
  for (int idx = tid; idx < 72*K; idx += 288){
    int o = idx / K, kk = idx % K;
    Ws[kk*72 + o] = W[idx];
  }
  const float* Ab = A + ((long)(b*TT + t0))*K;
  for (int idx = tid; idx < 128*K; idx += 288){
    int r = idx / K, kk = idx % K;
    As[r*KP + kk] = (r < nact) ? Ab[idx] : 0.f;
  }
  __syncthreads();
  const int og = tid % 18, tg = tid / 18;
  float acc[8][4];
  #pragma unroll
  for (int m=0;m<8;m++){ acc[m][0]=0.f;acc[m][1]=0.f;acc[m][2]=0.f;acc[m][3]=0.f; }
  #pragma unroll 4
  for (int kk=0; kk<K; kk++){
    float4 w4 = *(const float4*)&Ws[kk*72 + og*4];
    #pragma unroll
    for (int m=0;m<8;m++){
      float a = As[(tg + 16*m)*KP + kk];
      acc[m][0] = fmaf(a, w4.x, acc[m][0]);
      acc[m][1] = fmaf(a, w4.y, acc[m][1]);
      acc[m][2] = fmaf(a, w4.z, acc[m][2]);
      acc[m][3] = fmaf(a, w4.w, acc[m][3]);
    }
  }
  float4 bv = *(const float4*)&bias[og*4];
  __syncthreads();           // everyone done reading As -> reuse as Ys
  float* Ys = As;            // stride 73
  #pragma unroll
  for (int m=0;m<8;m++){
    int r = tg + 16*m;
    if (r < nact){
      const float4 res = *(const float4*)&g_h[((long)(b*TT + t0 + r))*DT + og*4];
      Ys[r*73 + og*4+0] = res.x + acc[m][0] + bv.x;
      Ys[r*73 + og*4+1] = res.y + acc[m][1] + bv.y;
      Ys[r*73 + og*4+2] = res.z + acc[m][2] + bv.z;
      Ys[r*73 + og*4+3] = res.w + acc[m][3] + bv.w;
    }
  }
  __syncthreads();
  int warp = tid/32, lane = tid%32;
  for (int tk=warp; tk<nact; tk+=9){
    float* y = &Ys[tk*73];
    float x0=y[lane], x1=y[lane+32], x2=(lane<8)?y[lane+64]:0.f;
    float mu = warp_sum(x0+x1+x2)*(1.0f/72.0f);
    float e0=x0-mu, e1=x1-mu, e2=(lane<8)?(x2-mu):0.f;
    float var = warp_sum(e0*e0+e1*e1+e2*e2)*(1.0f/72.0f);
    float rstd = rsqrtf(var+1e-5f);
    float* hout = &g_h[((long)(b*TT + t0 + tk))*DT];
    hout[lane]    = e0*rstd*gam[lane]   + bet[lane];
    hout[lane+32] = e1*rstd*gam[lane+32]+ bet[lane+32];
    if (lane<8) hout[lane+64] = e2*rstd*gam[lane+64]+bet[lane+64];
  }
}

// ---------------- encoder attention: lanes=queries, loop keys, two-pass ----------------
// grid (256, 4), block 256. Only s,t < len processed (masked keys are exact zeros).
__global__ __launch_bounds__(256) void k_attn2(const float* __restrict__ qkv,
                                               const int* __restrict__ lengths){
  extern __shared__ float sm[];
  float* Ks = sm;              // [215][20]
  float* Vs = sm + TT*20;      // [215][20]
  float* Qs = sm + 2*TT*20;    // [215][21]
  int b = blockIdx.x, h = blockIdx.y;
  int len = lengths[b];
  int tid = threadIdx.x;
  const float* base = qkv + ((long)b*TT)*216 + h*18;
  for (int idx = tid; idx < len*18; idx += 256){
    int s = idx/18, d = idx%18;
    const float* row = base + (long)s*216;
    Qs[s*21+d] = row[d];
    Ks[s*20+d] = row[72+d];
    Vs[s*20+d] = row[144+d];
  }
  for (int s = tid; s < len; s += 256){
    Ks[s*20+18]=0.f; Ks[s*20+19]=0.f; Vs[s*20+18]=0.f; Vs[s*20+19]=0.f;
  }
  __syncthreads();
  int w = tid>>5, lane = tid&31;
  int t = w*32 + lane;
  if (w*32 >= len) return;
  bool active = t < len;
  float q[20];
  #pragma unroll
  for (int j=0;j<20;j++) q[j]=0.f;
  if (active){
    #pragma unroll
    for (int j=0;j<18;j++) q[j] = Qs[t*21+j];
  }
  const float scale = 0.23570226039551584f; // 1/sqrt(18)
  float mx = -3.0e38f;
  for (int s=0; s<len; s++){
    const float4* kr = (const float4*)&Ks[s*20];
    float a0=0.f,a1=0.f,a2=0.f,a3=0.f;
    #pragma unroll
    for (int j=0;j<5;j++){
      float4 k4 = kr[j];
      a0 = fmaf(q[4*j+0], k4.x, a0);
      a1 = fmaf(q[4*j+1], k4.y, a1);
      a2 = fmaf(q[4*j+2], k4.z, a2);
      a3 = fmaf(q[4*j+3], k4.w, a3);
    }
    mx = fmaxf(mx, ((a0+a1)+(a2+a3))*scale);
  }
  float l = 0.f;
  float cx[20];
  #pragma unroll
  for (int j=0;j<20;j++) cx[j]=0.f;
  for (int s=0; s<len; s++){
    const float4* kr = (const float4*)&Ks[s*20];
    float a0=0.f,a1=0.f,a2=0.f,a3=0.f;
    #pragma unroll
    for (int j=0;j<5;j++){
      float4 k4 = kr[j];
      a0 = fmaf(q[4*j+0], k4.x, a0);
      a1 = fmaf(q[4*j+1], k4.y, a1);
      a2 = fmaf(q[4*j+2], k4.z, a2);
      a3 = fmaf(q[4*j+3], k4.w, a3);
    }
    float p = __expf(((a0+a1)+(a2+a3))*scale - mx);
    l += p;
    const float4* vr = (const float4*)&Vs[s*20];
    #pragma unroll
    for (int j=0;j<5;j++){
      float4 v4 = vr[j];
      cx[4*j+0] = fmaf(p, v4.x, cx[4*j+0]);
      cx[4*j+1] = fmaf(p, v4.y, cx[4*j+1]);
      cx[4*j+2] = fmaf(p, v4.z, cx[4*j+2]);
      cx[4*j+3] = fmaf(p, v4.w, cx[4*j+3]);
    }
  }
  if (active){
    float inv = 1.f/l;
    float* o = &g_ctx[((long)(b*TT + t))*DT + h*18];
    #pragma unroll
    for (int d=0;d<18;d++) o[d] = cx[d]*inv;
  }
}

// ---------------- pooling + static emb + MLP head ----------------
__global__ void k_head(const float* __restrict__ statp, const int* __restrict__ lengths,
                       const float* __restrict__ W_emb, const float* __restrict__ b_emb,
                       const float* __restrict__ w1, const float* __restrict__ b1,
                       const float* __restrict__ w2, const float* __restrict__ b2,
                       float* __restrict__ out){
  __shared__ float feat[108];
  __shared__ float hid[108];
  __shared__ float st[9];
  int b = blockIdx.x, tid = threadIdx.x;
  int len = lengths[b];
  if (tid < 9) st[tid] = statp[b*9+tid];
  __syncthreads();
  if (tid < 36){
    float acc = b_emb[tid];
    #pragma unroll
    for (int i=0;i<9;i++) acc = fmaf(st[i], W_emb[tid*9+i], acc);
    feat[72+tid] = acc;
  }
  if (tid < 72){
    float acc = 0.f;
    for (int t=0;t<len;t++) acc += g_h[((long)(b*TT + t))*DT + tid];
    feat[tid] = acc / ((float)len + 1.0f);
  }
  __syncthreads();
  for (int o=tid; o<108; o+=blockDim.x){
    float acc = b1[o];
    #pragma unroll 4
    for (int i=0;i<108;i++) acc = fmaf(feat[i], w1[o*108+i], acc);
    hid[o] = fmaxf(acc, 0.f);
  }
  __syncthreads();
  if (tid < 2){
    float acc = b2[tid];
    for (int i=0;i<108;i++) acc = fmaf(hid[i], w2[tid*108+i], acc);
    out[b*2+tid] = acc;
  }
}

// ---------------- host ----------------
extern "C" void kernel_launch(void* const* d_in, const int* in_sizes, int n_in,
                              void* d_out, int out_size){
  const float* src     = (const float*)d_in[0];
  const float* statp   = (const float*)d_in[1];
  const float* times   = (const float*)d_in[2];
  const int*   lengths = (const int*)  d_in[3];
  const float* W_enc   = (const float*)d_in[4];
  const float* b_enc   = (const float*)d_in[5];
  const float* W_emb   = (const float*)d_in[6];
  const float* b_emb   = (const float*)d_in[7];
  const float* Wq      = (const float*)d_in[8];
  const float* bq      = (const float*)d_in[9];
  const float* Wk      = (const float*)d_in[10];
  const float* bk      = (const float*)d_in[11];
  const float* Wv      = (const float*)d_in[12];
  const float* bv      = (const float*)d_in[13];
  const float* Wskip   = (const float*)d_in[14];
  const float* bskip   = (const float*)d_in[15];
  const float* enc_in_w  = (const float*)d_in[16];
  const float* enc_in_b  = (const float*)d_in[17];
  const float* enc_out_w = (const float*)d_in[18];
  const float* enc_out_b = (const float*)d_in[19];
  const float* ff1w    = (const float*)d_in[20];
  const float* ff1b    = (const float*)d_in[21];
  const float* ff2w    = (const float*)d_in[22];
  const float* ff2b    = (const float*)d_in[23];
  const float* ln1g    = (const float*)d_in[24];
  const float* ln1b    = (const float*)d_in[25];
  const float* ln2g    = (const float*)d_in[26];
  const float* ln2b    = (const float*)d_in[27];
  const float* mlp_w1  = (const float*)d_in[28];
  const float* mlp_b1  = (const float*)d_in[29];
  const float* mlp_w2  = (const float*)d_in[30];
  const float* mlp_b2  = (const float*)d_in[31];
  float* out = (float*)d_out;

  float *hB, *tmpB, *ctxB;
  cudaGetSymbolAddress((void**)&hB,   g_h);
  cudaGetSymbolAddress((void**)&tmpB, g_tmp);
  cudaGetSymbolAddress((void**)&ctxB, g_ctx);

  const int SM_QKV  = (72*72 + 128*72)*4;    // 57600
  const int SM_LN1  = (72*72 + 128*73)*4;    // 58112
  const int SM_FF1  = (72*128 + 128*72)*4;   // 73728
  const int SM_LN2  = (128*72 + 128*129)*4;  // 102912
  const int SM_ATT  = (TT*61)*4;             // 52460

  cudaFuncSetAttribute(k_gemm_rt<72,72,18,false>, cudaFuncAttributeMaxDynamicSharedMemorySize, SM_QKV);
  cudaFuncSetAttribute(k_gemm_rt<72,128,32,true>, cudaFuncAttributeMaxDynamicSharedMemorySize, SM_FF1);
  cudaFuncSetAttribute(k_gemmln_rt<72>,  cudaFuncAttributeMaxDynamicSharedMemorySize, SM_LN1);
  cudaFuncSetAttribute(k_gemmln_rt<128>, cudaFuncAttributeMaxDynamicSharedMemorySize, SM_LN2);
  cudaFuncSetAttribute(k_attn2, cudaFuncAttributeMaxDynamicSharedMemorySize, SM_ATT);

  k_combine<<<1,256>>>(Wq,bq,Wk,bk,Wv,bv,Wskip,bskip,W_enc,b_enc);
  k_embed<<<dim3(TT,2),128>>>(src, times);
  k_graph<<<BB,256>>>();
  k_gram<<<BB,256>>>();

  for (int l=0; l<2; l++){
    k_gemm_rt<72,72,18,false><<<dim3(2,BB,3),288,SM_QKV>>>(
        hB, enc_in_w + (long)l*216*72, enc_in_b + l*216, tmpB, 216, lengths);
    k_attn2<<<dim3(BB,4),256,SM_ATT>>>(tmpB, lengths);
    k_gemmln_rt<72><<<dim3(2,BB),288,SM_LN1>>>(
        ctxB, enc_out_w + (long)l*72*72, enc_out_b + l*72, ln1g + l*72, ln1b + l*72, lengths);
    k_gemm_rt<72,128,32,true><<<dim3(2,BB,1),512,SM_FF1>>>(
        hB, ff1w + (long)l*128*72, ff1b + l*128, tmpB, 128, lengths);
    k_gemmln_rt<128><<<dim3(2,BB),288,SM_LN2>>>(
        tmpB, ff2w + (long)l*72*128, ff2b + l*72, ln2g + l*72, ln2b + l*72, lengths);
  }

  k_head<<<BB,128>>>(statp, lengths, W_emb, b_emb, mlp_w1, mlp_b1, mlp_w2, mlp_b2, out);
  k_distfin<<<1,256>>>(out, out_size);
}

// round 4
// speedup vs baseline: 2.5835x; 1.1885x over previous
#include <cuda_runtime.h>
#include <math.h>

#define TT 215
#define BB 256
#define NTOK (TT*BB)      // 55040
#define DT 72

// ---------------- scratch (device globals, alloc-free) ----------------
__device__ float g_h[NTOK*DT];        // hidden state [b][t][72]
__device__ float g_tmp[NTOK*216];     // qkv (216) / ff1 (128) scratch
__device__ float g_ctx[NTOK*DT];      // attention context [b][t][72]
__device__ float g_qkvg[3*36*BB*36];  // graph q,k,v  [m][node][b][e]
__device__ float g_AT[1296*BB];       // graph attention flattened, [e][b]
__device__ float g_sq[BB];
__device__ float g_part[BB];
__device__ float g_Wc[4*36*36];       // combined q/k/v/skip weights
__device__ float g_bc[4*36];
__device__ int   g_off[BB];           // exclusive prefix of lengths
__device__ int   g_nrows;             // total active rows
__device__ int   g_rowidx[NTOK];      // compact row -> b*TT+t

__device__ __forceinline__ float warp_sum(float v){
  #pragma unroll
  for (int o=16;o;o>>=1) v += __shfl_xor_sync(0xffffffffu,v,o);
  return v;
}

// ---------------- 0: fold x-projection into q/k/v/skip + length scan ----------------
__global__ void k_combine(const float* __restrict__ Wq, const float* __restrict__ bq,
                          const float* __restrict__ Wk, const float* __restrict__ bk,
                          const float* __restrict__ Wv, const float* __restrict__ bv,
                          const float* __restrict__ Ws, const float* __restrict__ bs,
                          const float* __restrict__ Wenc, const float* __restrict__ benc,
                          const int* __restrict__ lengths){
  __shared__ int sc[256];
  int tid = threadIdx.x;
  int len = lengths[tid];
  sc[tid] = len; __syncthreads();
  for (int d=1; d<256; d<<=1){
    int v = 0; if (tid >= d) v = sc[tid-d];
    __syncthreads(); sc[tid] += v; __syncthreads();
  }
  g_off[tid] = sc[tid] - len;
  if (tid == 255) g_nrows = sc[255];

  const float* Wm[4] = {Wq,Wk,Wv,Ws};
  const float* bm[4] = {bq,bk,bv,bs};
  for (int idx = tid; idx < 4*36*36; idx += blockDim.x){
    int m = idx/1296, r = idx%1296, e = r/36, i = r%36;
    float acc = 0.f;
    for (int kk=0; kk<36; kk++) acc += Wm[m][e*36+kk]*Wenc[kk*36+i];
    g_Wc[idx] = 6.0f*acc;
  }
  for (int idx = tid; idx < 4*36; idx += blockDim.x){
    int m = idx/36, e = idx%36;
    float acc = 0.f;
    for (int kk=0; kk<36; kk++) acc += Wm[m][e*36+kk]*benc[kk];
    g_bc[idx] = 6.0f*acc + bm[m][e];
  }
}

__global__ void k_fill(const int* __restrict__ lengths){
  int b = blockIdx.x;
  int len = lengths[b];
  int off = g_off[b];
  for (int t = threadIdx.x; t < len; t += blockDim.x)
    g_rowidx[off + t] = b*TT + t;
}

// ---------------- 1: skip + pe -> h, graph qkv for t<36 ----------------
__global__ __launch_bounds__(128) void k_embed(const float* __restrict__ src,
                                               const float* __restrict__ times,
                                               const int* __restrict__ lengths){
  __shared__ float Wt[4*36*36];   // [m][i][e] transposed
  __shared__ float bcs[4*36];
  __shared__ float srcs[128*37];
  __shared__ float ts_s[18];
  int t = blockIdx.x; int b0 = blockIdx.y*128; int tid = threadIdx.x;
  for (int idx=tid; idx<4*1296; idx+=128){
    int m = idx/1296, r = idx%1296, e = r/36, i2 = r%36;
    Wt[m*1296 + i2*36 + e] = g_Wc[m*1296 + e*36 + i2];
  }
  for (int idx=tid; idx<144; idx+=128) bcs[idx]=g_bc[idx];
  if (tid<18) ts_s[tid] = (float)pow(215.0,(double)tid/17.0);
  for (int idx=tid; idx<128*36; idx+=128){
    int bl = idx/36, i2 = idx%36;
    srcs[bl*37+i2] = src[((long)t*BB + b0+bl)*72 + i2];
  }
  __syncthreads();
  int b = b0 + tid;
  int len = lengths[b];
  bool act = (t < len) || (t < 36);
  if (!act) return;
  float sr[36];
  #pragma unroll
  for (int i2=0;i2<36;i2++) sr[i2] = srcs[tid*37+i2];
  float tv = times[(long)t*BB + b];
  float* hrow = &g_h[((long)b*TT + t)*DT];
  #pragma unroll
  for (int d=0; d<18; d++){
    float s, c; sincosf(tv/ts_s[d], &s, &c);
    hrow[36+d] = s; hrow[54+d] = c;
  }
  int mmax = (t<36) ? 4 : 1;
  for (int mm=0; mm<mmax; mm++){
    int m = (mm==0)?3:(mm-1);
    float acc[36];
    #pragma unroll
    for (int e=0;e<36;e++) acc[e] = bcs[m*36+e];
    #pragma unroll
    for (int kk=0;kk<36;kk++){
      float a = sr[kk];
      const float4* wr = (const float4*)&Wt[m*1296 + kk*36];
      #pragma unroll
      for (int j=0;j<9;j++){
        float4 w4 = wr[j];
        acc[4*j+0] = fmaf(a, w4.x, acc[4*j+0]);
        acc[4*j+1] = fmaf(a, w4.y, acc[4*j+1]);
        acc[4*j+2] = fmaf(a, w4.z, acc[4*j+2]);
        acc[4*j+3] = fmaf(a, w4.w, acc[4*j+3]);
      }
    }
    float4* o = (m==3) ? (float4*)hrow
                       : (float4*)&g_qkvg[(((long)m*36+t)*BB + b)*36];
    #pragma unroll
    for (int j=0;j<9;j++){ float4 v; v.x=acc[4*j]; v.y=acc[4*j+1]; v.z=acc[4*j+2]; v.w=acc[4*j+3]; o[j]=v; }
  }
}

// ---------------- 2: graph attention per batch (36x36) ----------------
__global__ void k_graph(){
  __shared__ float qs[36*37], ks[36*37], vs[36*37], As[36*37];
  __shared__ float red[256];
  int b = blockIdx.x, tid = threadIdx.x;
  for (int idx=tid; idx<1296; idx+=256){
    int n = idx/36, e = idx%36;
    qs[n*37+e] = g_qkvg[((0L*36+n)*BB + b)*36 + e];
    ks[n*37+e] = g_qkvg[((1L*36+n)*BB + b)*36 + e];
    vs[n*37+e] = g_qkvg[((2L*36+n)*BB + b)*36 + e];
  }
  __syncthreads();
  for (int idx=tid; idx<1296; idx+=256){
    int i = idx/36, j = idx%36;
    float acc = 0.f;
    #pragma unroll
    for (int e=0;e<36;e++) acc = fmaf(qs[i*37+e], ks[j*37+e], acc);
    As[i*37+j] = acc*(1.0f/6.0f);
  }
  __syncthreads();
  int warp = tid/32, lane = tid%32;
  for (int i=warp; i<36; i+=8){
    float v1 = As[i*37+lane];
    float v2 = (lane<4) ? As[i*37+32+lane] : -3e38f;
    float mx = fmaxf(v1,v2);
    #pragma unroll
    for (int o=16;o;o>>=1) mx = fmaxf(mx,__shfl_xor_sync(0xffffffffu,mx,o));
    float p1 = __expf(v1-mx);
    float p2 = (lane<4) ? __expf(v2-mx) : 0.f;
    float s = warp_sum(p1+p2);
    float inv = 1.f/s;
    As[i*37+lane] = p1*inv;
    if (lane<4) As[i*37+32+lane] = p2*inv;
  }
  __syncthreads();
  float sqacc = 0.f;
  for (int idx=tid; idx<1296; idx+=256){
    int i = idx/36, j = idx%36;
    float a = As[i*37+j];
    g_AT[(long)idx*BB + b] = a;
    sqacc += a*a;
  }
  red[tid] = sqacc; __syncthreads();
  for (int s2=128; s2>0; s2>>=1){
    if (tid<s2) red[tid]+=red[tid+s2];
    __syncthreads();
  }
  if (tid==0) g_sq[b] = red[0];
  for (int idx=tid; idx<1296; idx+=256){
    int i = idx/36, e = idx%36;
    float acc = 0.f;
    #pragma unroll
    for (int j=0;j<36;j++) acc = fmaf(As[i*37+j], vs[j*37+e], acc);
    g_h[((long)(b*TT + i))*DT + e] += acc;
  }
}

// ---------------- 3: gram / pairwise distance partials ----------------
// grid 64 blocks, each handles 4 b1 rows; 256 threads = b2
__global__ void k_gram(){
  __shared__ float arT[1296*4];   // [e][4]
  __shared__ float red[256];
  int g = blockIdx.x, tid = threadIdx.x;
  for (int idx=tid; idx<1296*4; idx+=256){
    int e = idx>>2, m = idx&3;
    arT[idx] = g_AT[(long)e*BB + g*4 + m];
  }
  __syncthreads();
  int b2 = tid;
  float a0=0.f,a1=0.f,a2=0.f,a3=0.f;
  for (int e=0;e<1296;e++){
    float v = g_AT[(long)e*BB + b2];
    float4 a4 = *(const float4*)&arT[e*4];
    a0=fmaf(a4.x,v,a0); a1=fmaf(a4.y,v,a1); a2=fmaf(a4.z,v,a2); a3=fmaf(a4.w,v,a3);
  }
  float sq2 = g_sq[b2];
  float acc[4] = {a0,a1,a2,a3};
  #pragma unroll
  for (int m=0;m<4;m++){
    int b1 = g*4+m;
    float d2 = g_sq[b1] + sq2 - 2.0f*acc[m];
    d2 = fmaxf(d2, 0.f);
    float c = (d2 > 0.f) ? sqrtf(d2) : 0.f;
    red[tid] = c; __syncthreads();
    for (int s2=128; s2>0; s2>>=1){
      if (tid<s2) red[tid]+=red[tid+s2];
      __syncthreads();
    }
    if (tid==0) g_part[b1] = red[0];
    __syncthreads();
  }
}

__global__ void k_distfin(float* __restrict__ out, int out_size){
  __shared__ float red[256];
  int tid = threadIdx.x;
  red[tid] = g_part[tid]; __syncthreads();
  for (int s2=128; s2>0; s2>>=1){
    if (tid<s2) red[tid]+=red[tid+s2];
    __syncthreads();
  }
  if (tid==0) out[out_size-1] = red[0] * (1.0f/65536.0f);
}

// ---------------- compact register-tiled GEMM: C[ridx]@ = A[ridx]@W.T + b ----------------
// 128 compact rows per block; TM=8 (stride 16), TN=4; blockDim = 16*(OC/4).
template<int K, int OC, int NZ, bool RELU>
__global__ __launch_bounds__(512) void k_gemm_c(
    const float* __restrict__ A, const float* __restrict__ W,
    const float* __restrict__ bias, float* __restrict__ C, int ldc){
  constexpr int KP = K+1;
  constexpr int NOG = OC/4;
  extern __shared__ float sm[];
  float* Ws = sm;                       // [K][OC]
  float* As = sm + K*OC;                // [128][KP]
  int*   ridx = (int*)(As + 128*KP);    // [128]
  const int nrows = g_nrows;
  const int t0 = blockIdx.x*128;
  if (t0 >= nrows) return;
  const int nact = min(128, nrows - t0);
  const int tid = threadIdx.x;
  if (tid < 128) ridx[tid] = (tid < nact) ? g_rowidx[t0+tid] : 0;
  __syncthreads();
  for (int idx = tid; idx < OC*K; idx += blockDim.x){
    int o = idx / K, kk = idx % K;
    Ws[kk*OC + o] = W[idx];
  }
  for (int idx = tid; idx < 128*K; idx += blockDim.x){
    int r = idx / K, kk = idx % K;
    As[r*KP + kk] = (r < nact) ? A[(long)ridx[r]*K + kk] : 0.f;
  }
  __syncthreads();
  const int og = tid % NOG, tg = tid / NOG;
  for (int z=0; z<NZ; z++){
    float acc[8][4];
    #pragma unroll
    for (int m=0;m<8;m++){ acc[m][0]=0.f;acc[m][1]=0.f;acc[m][2]=0.f;acc[m][3]=0.f; }
    #pragma unroll 4
    for (int kk=0; kk<K; kk++){
      float4 w4 = *(const float4*)&Ws[kk*OC + og*4];
      #pragma unroll
      for (int m=0;m<8;m++){
        float a = As[(tg + 16*m)*KP + kk];
        acc[m][0] = fmaf(a, w4.x, acc[m][0]);
        acc[m][1] = fmaf(a, w4.y, acc[m][1]);
        acc[m][2] = fmaf(a, w4.z, acc[m][2]);
        acc[m][3] = fmaf(a, w4.w, acc[m][3]);
      }
    }
    float4 bv = *(const float4*)&bias[(long)z*OC + og*4];
    #pragma unroll
    for (int m=0;m<8;m++){
      int r = tg + 16*m;
      if (r < nact){
        float4 o4;
        o4.x = acc[m][0]+bv.x; o4.y = acc[m][1]+bv.y;
        o4.z = acc[m][2]+bv.z; o4.w = acc[m][3]+bv.w;
        if (RELU){ o4.x=fmaxf(o4.x,0.f); o4.y=fmaxf(o4.y,0.f); o4.z=fmaxf(o4.z,0.f); o4.w=fmaxf(o4.w,0.f); }
        *(float4*)&C[(long)ridx[r]*ldc + z*OC + og*4] = o4;
      }
    }
    __syncthreads();
    if (z+1 < NZ){
      const float* Wp = W + (long)(z+1)*OC*K;
      for (int idx = tid; idx < OC*K; idx += blockDim.x){
        int o = idx / K, kk = idx % K;
        Ws[kk*OC + o] = Wp[idx];
      }
      __syncthreads();
    }
  }
}

// ---------------- compact GEMM + residual(g_h) + LayerNorm -> g_h ----------------
template<int K>
__global__ __launch_bounds__(288) void k_gemmln_c(
    const float* __restrict__ A, const float* __restrict__ W,
    const float* __restrict__ bias, const float* __restrict__ gam,
    const float* __restrict__ bet){
  constexpr int KP = K+1;
  extern __shared__ float sm[];
  float* Ws = sm;                       // [K][72]
  float* As = sm + K*72;                // [128][KP]
  int*   ridx = (int*)(As + 128*KP);
  const int nrows = g_nrows;
  const int t0 = blockIdx.x*128;
  if (t0 >= nrows) return;
  const int nact = min(128, nrows - t0);
  const int tid = threadIdx.x;
  if (tid < 128) ridx[tid] = (tid < nact) ? g_rowidx[t0+tid] : 0;
  __syncthreads();
  for (int idx = tid; idx < 72*K; idx += 288){
    int o = idx / K, kk = idx % K;
    Ws[kk*72 + o] = W[idx];
  }
  for (int idx = tid; idx < 128*K; idx += 288){
    int r = idx / K, kk = idx % K;
    As[r*KP + kk] = (r < nact) ? A[(long)ridx[r]*K + kk] : 0.f;
  }
  __syncthreads();
  const int og = tid % 18, tg = tid / 18;
  float acc[8][4];
  #pragma unroll
  for (int m=0;m<8;m++){ acc[m][0]=0.f;acc[m][1]=0.f;acc[m][2]=0.f;acc[m][3]=0.f; }
  #pragma unroll 4
  for (int kk=0; kk<K; kk++){
    float4 w4 = *(const float4*)&Ws[kk*72 + og*4];
    #pragma unroll
    for (int m=0;m<8;m++){
      float a = As[(tg + 16*m)*KP + kk];
      acc[m][0] = fmaf(a, w4.x, acc[m][0]);
      acc[m][1] = fmaf(a, w4.y, acc[m][1]);
      acc[m][2] = fmaf(a, w4.z, acc[m][2]);
      acc[m][3] = fmaf(a, w4.w, acc[m][3]);
    }
  }
  float4 bv = *(const float4*)&bias[og*4];
  __syncthreads();           // done reading As -> reuse as Ys
  float* Ys = As;            // stride 73
  #pragma unroll
  for (int m=0;m<8;m++){
    int r = tg + 16*m;
    if (r < nact){
      const float4 res = *(const float4*)&g_h[(long)ridx[r]*DT + og*4];
      Ys[r*73 + og*4+0] = res.x + acc[m][0] + bv.x;
      Ys[r*73 + og*4+1] = res.y + acc[m][1] + bv.y;
      Ys[r*73 + og*4+2] = res.z + acc[m][2] + bv.z;
      Ys[r*73 + og*4+3] = res.w + acc[m][3] + bv.w;
    }
  }
  __syncthreads();
  int warp = tid/32, lane = tid%32;
  for (int tk=warp; tk<nact; tk+=9){
    float* y = &Ys[tk*73];
    float x0=y[lane], x1=y[lane+32], x2=(lane<8)?y[lane+64]:0.f;
    float mu = warp_sum(x0+x1+x2)*(1.0f/72.0f);
    float e0=x0-mu, e1=x1-mu, e2=(lane<8)?(x2-mu):0.f;
    float var = warp_sum(e0*e0+e1*e1+e2*e2)*(1.0f/72.0f);
    float rstd = rsqrtf(var+1e-5f);
    float* hout = &g_h[(long)ridx[tk]*DT];
    hout[lane]    = e0*rstd*gam[lane]   + bet[lane];
    hout[lane+32] = e1*rstd*gam[lane+32]+ bet[lane+32];
    if (lane<8) hout[lane+64] = e2*rstd*gam[lane+64]+bet[lane+64];
  }
}

// ---------------- encoder attention: online softmax, lanes=queries ----------------
__global__ __launch_bounds__(256) void k_attn2(const float* __restrict__ qkv,
                                               const int* __restrict__ lengths){
  extern __shared__ float sm[];
  float* Ks = sm;              // [215][20]
  float* Vs = sm + TT*20;      // [215][20]
  float* Qs = sm + 2*TT*20;    // [215][21]
  int b = blockIdx.x, h = blockIdx.y;
  int len = lengths[b];
  int tid = threadIdx.x;
  const float* base = qkv + ((long)b*TT)*216 + h*18;
  for (int idx = tid; idx < len*18; idx += 256){
    int s = idx/18, d = idx%18;
    const float* row = base + (long)s*216;
    Qs[s*21+d] = row[d];
    Ks[s*20+d] = row[72+d];
    Vs[s*20+d] = row[144+d];
  }
  for (int s = tid; s < len; s += 256){
    Ks[s*20+18]=0.f; Ks[s*20+19]=0.f; Vs[s*20+18]=0.f; Vs[s*20+19]=0.f;
  }
  __syncthreads();
  int w = tid>>5, lane = tid&31;
  int t = w*32 + lane;
  if (w*32 >= len) return;
  bool active = t < len;
  float q[20];
  #pragma unroll
  for (int j=0;j<20;j++) q[j]=0.f;
  if (active){
    #pragma unroll
    for (int j=0;j<18;j++) q[j] = Qs[t*21+j];
  }
  const float scale = 0.23570226039551584f; // 1/sqrt(18)
  float mx = -3.0e38f, l = 0.f;
  float cx[20];
  #pragma unroll
  for (int j=0;j<20;j++) cx[j]=0.f;
  for (int s=0; s<len; s++){
    const float4* kr = (const float4*)&Ks[s*20];
    float a0=0.f,a1=0.f,a2=0.f,a3=0.f;
    #pragma unroll
    for (int j=0;j<5;j++){
      float4 k4 = kr[j];
      a0 = fmaf(q[4*j+0], k4.x, a0);
      a1 = fmaf(q[4*j+1], k4.y, a1);
      a2 = fmaf(q[4*j+2], k4.z, a2);
      a3 = fmaf(q[4*j+3], k4.w, a3);
    }
    float sc = ((a0+a1)+(a2+a3))*scale;
    if (sc > mx){
      float alpha = __expf(mx - sc);   // 0 on first hit
      l *= alpha;
      #pragma unroll
      for (int j=0;j<20;j++) cx[j] *= alpha;
      mx = sc;
    }
    float p = __expf(sc - mx);
    l += p;
    const float4* vr = (const float4*)&Vs[s*20];
    #pragma unroll
    for (int j=0;j<5;j++){
      float4 v4 = vr[j];
      cx[4*j+0] = fmaf(p, v4.x, cx[4*j+0]);
      cx[4*j+1] = fmaf(p, v4.y, cx[4*j+1]);
      cx[4*j+2] = fmaf(p, v4.z, cx[4*j+2]);
      cx[4*j+3] = fmaf(p, v4.w, cx[4*j+3]);
    }
  }
  if (active){
    float inv = 1.f/l;
    float* o = &g_ctx[((long)(b*TT + t))*DT + h*18];
    #pragma unroll
    for (int d=0;d<18;d++) o[d] = cx[d]*inv;
  }
}

// ---------------- pooling + static emb + MLP head ----------------
__global__ void k_head(const float* __restrict__ statp, const int* __restrict__ lengths,
                       const float* __restrict__ W_emb, const float* __restrict__ b_emb,
                       const float* __restrict__ w1, const float* __restrict__ b1,
                       const float* __restrict__ w2, const float* __restrict__ b2,
                       float* __restrict__ out){
  __shared__ float feat[108];
  __shared__ float hid[108];
  __shared__ float st[9];
  int b = blockIdx.x, tid = threadIdx.x;
  int len = lengths[b];
  if (tid < 9) st[tid] = statp[b*9+tid];
  __syncthreads();
  if (tid < 36){
    float acc = b_emb[tid];
    #pragma unroll
    for (int i=0;i<9;i++) acc = fmaf(st[i], W_emb[tid*9+i], acc);
    feat[72+tid] = acc;
  }
  if (tid < 72){
    float acc = 0.f;
    for (int t=0;t<len;t++) acc += g_h[((long)(b*TT + t))*DT + tid];
    feat[tid] = acc / ((float)len + 1.0f);
  }
  __syncthreads();
  for (int o=tid; o<108; o+=blockDim.x){
    float acc = b1[o];
    #pragma unroll 4
    for (int i=0;i<108;i++) acc = fmaf(feat[i], w1[o*108+i], acc);
    hid[o] = fmaxf(acc, 0.f);
  }
  __syncthreads();
  if (tid < 2){
    float acc = b2[tid];
    for (int i=0;i<108;i++) acc = fmaf(hid[i], w2[tid*108+i], acc);
    out[b*2+tid] = acc;
  }
}

// ---------------- host ----------------
extern "C" void kernel_launch(void* const* d_in, const int* in_sizes, int n_in,
                              void* d_out, int out_size){
  const float* src     = (const float*)d_in[0];
  const float* statp   = (const float*)d_in[1];
  const float* times   = (const float*)d_in[2];
  const int*   lengths = (const int*)  d_in[3];
  const float* W_enc   = (const float*)d_in[4];
  const float* b_enc   = (const float*)d_in[5];
  const float* W_emb   = (const float*)d_in[6];
  const float* b_emb   = (const float*)d_in[7];
  const float* Wq      = (const float*)d_in[8];
  const float* bq      = (const float*)d_in[9];
  const float* Wk      = (const float*)d_in[10];
  const float* bk      = (const float*)d_in[11];
  const float* Wv      = (const float*)d_in[12];
  const float* bv      = (const float*)d_in[13];
  const float* Wskip   = (const float*)d_in[14];
  const float* bskip   = (const float*)d_in[15];
  const float* enc_in_w  = (const float*)d_in[16];
  const float* enc_in_b  = (const float*)d_in[17];
  const float* enc_out_w = (const float*)d_in[18];
  const float* enc_out_b = (const float*)d_in[19];
  const float* ff1w    = (const float*)d_in[20];
  const float* ff1b    = (const float*)d_in[21];
  const float* ff2w    = (const float*)d_in[22];
  const float* ff2b    = (const float*)d_in[23];
  const float* ln1g    = (const float*)d_in[24];
  const float* ln1b    = (const float*)d_in[25];
  const float* ln2g    = (const float*)d_in[26];
  const float* ln2b    = (const float*)d_in[27];
  const float* mlp_w1  = (const float*)d_in[28];
  const float* mlp_b1  = (const float*)d_in[29];
  const float* mlp_w2  = (const float*)d_in[30];
  const float* mlp_b2  = (const float*)d_in[31];
  float* out = (float*)d_out;

  float *hB, *tmpB, *ctxB;
  cudaGetSymbolAddress((void**)&hB,   g_h);
  cudaGetSymbolAddress((void**)&tmpB, g_tmp);
  cudaGetSymbolAddress((void**)&ctxB, g_ctx);

  const int GX = (NTOK + 127)/128;           // 430
  const int SM_QKV  = (72*72 + 128*73)*4 + 512;
  const int SM_LN1  = (72*72 + 128*73)*4 + 512;
  const int SM_FF1  = (72*128 + 128*73)*4 + 512;
  const int SM_LN2  = (128*72 + 128*129)*4 + 512;
  const int SM_ATT  = (TT*61)*4;

  cudaFuncSetAttribute(k_gemm_c<72,72,3,false>, cudaFuncAttributeMaxDynamicSharedMemorySize, SM_QKV);
  cudaFuncSetAttribute(k_gemm_c<72,128,1,true>, cudaFuncAttributeMaxDynamicSharedMemorySize, SM_FF1);
  cudaFuncSetAttribute(k_gemmln_c<72>,  cudaFuncAttributeMaxDynamicSharedMemorySize, SM_LN1);
  cudaFuncSetAttribute(k_gemmln_c<128>, cudaFuncAttributeMaxDynamicSharedMemorySize, SM_LN2);
  cudaFuncSetAttribute(k_attn2, cudaFuncAttributeMaxDynamicSharedMemorySize, SM_ATT);

  k_combine<<<1,256>>>(Wq,bq,Wk,bk,Wv,bv,Wskip,bskip,W_enc,b_enc,lengths);
  k_fill<<<BB,256>>>(lengths);
  k_embed<<<dim3(TT,2),128>>>(src, times, lengths);
  k_graph<<<BB,256>>>();
  k_gram<<<64,256>>>();

  for (int l=0; l<2; l++){
    k_gemm_c<72,72,3,false><<<GX,288,SM_QKV>>>(
        hB, enc_in_w + (long)l*216*72, enc_in_b + l*216, tmpB, 216);
    k_attn2<<<dim3(BB,4),256,SM_ATT>>>(tmpB, lengths);
    k_gemmln_c<72><<<GX,288,SM_LN1>>>(
        ctxB, enc_out_w + (long)l*72*72, enc_out_b + l*72, ln1g + l*72, ln1b + l*72);
    k_gemm_c<72,128,1,true><<<GX,512,SM_FF1>>>(
        hB, ff1w + (long)l*128*72, ff1b + l*128, tmpB, 128);
    k_gemmln_c<128><<<GX,288,SM_LN2>>>(
        tmpB, ff2w + (long)l*72*128, ff2b + l*72, ln2g + l*72, ln2b + l*72);
  }

  k_head<<<BB,128>>>(statp, lengths, W_emb, b_emb, mlp_w1, mlp_b1, mlp_w2, mlp_b2, out);
  k_distfin<<<1,256>>>(out, out_size);
}